// round 9
// baseline (speedup 1.0000x reference)
#include <cuda_runtime.h>

#define BB 128
#define SS 512
#define KK 4
#define DD 300
#define CC 20
#define NN 10000

// K1: thread = (dc 0..4, pair 0..15, cg 0..3) -> 320 threads, 32 nodes/block
#define DSPLIT 5
#define DCH (DD / DSPLIT)          // 60
#define P1_TPB 320
#define P1_NODES 32
#define P1_GRID ((NN + P1_NODES - 1) / P1_NODES)   // 313

// K2: grid (GCH s-chunks, BB), 320 threads
#define GCH 4
#define SCH (SS / GCH)             // 128 s-positions per block
#define G_TPB 320
#define G_SGRP 16                  // 320 / CC

__device__ float g_P[NN * CC];                 // P = node_emb @ fc_w^T (800 KB)
__device__ float g_part[BB * GCH * CC];        // per-(b,chunk) logit partials
__device__ unsigned int g_done[BB];            // zero-init; self-resets each call

// ---------------------------------------------------------------------------
// K1: P[n,c] = sum_d E[n,d]*W[c,d], split-D reduced in-block.
// unroll capped at 3 -> ~6 LDG.128 in flight per thread (avoids L1tex-queue
// contention / CTA spread from giant front-batched load groups).
// ---------------------------------------------------------------------------
__global__ void __launch_bounds__(P1_TPB, 2) p_kernel(
    const float* __restrict__ node_emb, const float* __restrict__ fc_w)
{
    __shared__ float sF[DSPLIT * CC * DCH];          // 24 KB, [dc][c][d]
    __shared__ float sAcc[DSPLIT][P1_NODES * CC];    // 12.8 KB

    const int t = threadIdx.x;

    for (int i = t; i < DSPLIT * CC * DCH; i += P1_TPB) {
        const int dc = i / (CC * DCH);
        const int r  = i % (CC * DCH);
        const int c  = r / DCH, d = r % DCH;
        sF[i] = fc_w[c * DD + dc * DCH + d];
    }
    __syncthreads();

    const int dc = t / 64;                 // 0..4
    const int w  = t % 64;
    const int pr = w >> 2;                 // 0..15 node-pair
    const int cg = w & 3;                  // 0..3  class-group (5 classes)
    const int n0 = blockIdx.x * P1_NODES + pr * 2;
    const int d0 = dc * DCH;

    if (n0 < NN) {                         // NN even -> pair never splits
        const float4* __restrict__ e0 = (const float4*)(node_emb + (size_t)n0 * DD + d0);
        const float4* __restrict__ e1 = (const float4*)(node_emb + (size_t)(n0 + 1) * DD + d0);
        const float4* __restrict__ f4 = (const float4*)(sF + dc * CC * DCH + cg * 5 * DCH);

        float a0[5] = {0.f, 0.f, 0.f, 0.f, 0.f};
        float a1[5] = {0.f, 0.f, 0.f, 0.f, 0.f};
        #pragma unroll 3
        for (int dq = 0; dq < DCH / 4; dq++) {       // 15 iters
            const float4 v0 = e0[dq];
            const float4 v1 = e1[dq];
            #pragma unroll
            for (int c5 = 0; c5 < 5; c5++) {
                const float4 fv = f4[c5 * (DCH / 4) + dq];
                a0[c5] += v0.x * fv.x + v0.y * fv.y + v0.z * fv.z + v0.w * fv.w;
                a1[c5] += v1.x * fv.x + v1.y * fv.y + v1.z * fv.z + v1.w * fv.w;
            }
        }
        #pragma unroll
        for (int c5 = 0; c5 < 5; c5++) {
            sAcc[dc][(pr * 2    ) * CC + cg * 5 + c5] = a0[c5];
            sAcc[dc][(pr * 2 + 1) * CC + cg * 5 + c5] = a1[c5];
        }
    }
    __syncthreads();

    const int base = blockIdx.x * P1_NODES * CC;
    for (int i = t; i < P1_NODES * CC; i += P1_TPB) {
        if (base + i < NN * CC) {
            float s = sAcc[0][i];
            #pragma unroll
            for (int d = 1; d < DSPLIT; d++) s += sAcc[d][i];
            g_P[base + i] = s;
        }
    }
}

// ---------------------------------------------------------------------------
// K2: block (ch,b) handles 128 s-positions. Chain-broken staging: EW indices
// streamed into smem first, then edge_w gathers issued fully independently.
// Last-arriving chunk block per b combines partials + softmax (no 3rd kernel).
// ---------------------------------------------------------------------------
__global__ void __launch_bounds__(G_TPB) gather_kernel(
    const int* __restrict__ X, const int* __restrict__ NX, const int* __restrict__ EW,
    const float* __restrict__ edge_w, const float* __restrict__ node_w,
    const float* __restrict__ fc_b, float* __restrict__ out)
{
    __shared__ int   sX[SCH];              // 0.5 KB
    __shared__ float sNW[SCH];
    __shared__ int   sNX[SCH * KK];        // 2 KB
    __shared__ int   sEWi[SCH * KK];       // 2 KB (EW indices)
    __shared__ float sEW[SCH * KK];        // 2 KB (gathered edge weights)
    __shared__ float sred[G_SGRP][CC];     // 1.25 KB

    const int ch = blockIdx.x;
    const int b  = blockIdx.y;
    const int s0 = ch * SCH;
    const int t  = threadIdx.x;

    // Stage 1: coalesced streaming loads of all indices (no dependent chains)
    for (int i = t; i < SCH * KK; i += G_TPB) sEWi[i] = EW[(b * SS + s0) * KK + i];
    for (int i = t; i < SCH * KK; i += G_TPB) sNX[i]  = NX[(b * SS + s0) * KK + i];
    for (int i = t; i < SCH; i += G_TPB)      sX[i]   = X[b * SS + s0 + i];
    __syncthreads();

    // Stage 2: fully independent random gathers (1.6 per thread, max MLP)
    for (int i = t; i < SCH * KK; i += G_TPB) sEW[i] = __ldg(&edge_w[sEWi[i]]);
    for (int i = t; i < SCH; i += G_TPB)      sNW[i] = __ldg(&node_w[sX[i]]);
    __syncthreads();

    // Main: thread (g,c) = class c over 8 s-positions; 80B row-gathers on P (L2)
    const int g = t / CC, c = t % CC;
    float acc = 0.f;
    #pragma unroll 4
    for (int i = 0; i < SCH / G_SGRP; i++) {       // 8
        const int s = g + i * G_SGRP;
        const float nw = sNW[s];
        float m = 0.f;
        #pragma unroll
        for (int k = 0; k < KK; k++)
            m += sEW[s * KK + k] * __ldg(&g_P[sNX[s * KK + k] * CC + c]);
        acc += (1.f - nw) * m + nw * __ldg(&g_P[sX[s] * CC + c]);
    }
    sred[g][c] = acc;
    __syncthreads();

    #pragma unroll
    for (int off = G_SGRP / 2; off > 0; off >>= 1) {
        if (g < off) sred[g][c] += sred[g + off][c];
        __syncthreads();
    }

    // Publish partial; last arriver for this b finalizes (fixed-order sum).
    if (t < CC) g_part[(b * GCH + ch) * CC + t] = sred[0][t];
    __syncthreads();

    if (t < 32) {
        unsigned last = 0;
        if (t == 0) {
            __threadfence();                               // release my partial
            last = (atomicAdd(&g_done[b], 1u) == GCH - 1) ? 1u : 0u;
        }
        last = __shfl_sync(0xffffffffu, last, 0);
        if (last) {
            if (t == 0) {
                g_done[b] = 0;                             // reset for next replay
                __threadfence();                           // acquire others' partials
            }
            __syncwarp();
            float l = -1e30f;
            if (t < CC) {
                float s = fc_b[t];
                #pragma unroll
                for (int q = 0; q < GCH; q++)
                    s += g_part[(b * GCH + q) * CC + t];
                l = fmaxf(s, 0.f);
            }
            float mx = l;
            #pragma unroll
            for (int o = 16; o; o >>= 1) mx = fmaxf(mx, __shfl_xor_sync(0xffffffffu, mx, o));
            const float e = (t < CC) ? __expf(l - mx) : 0.f;
            float sum = e;
            #pragma unroll
            for (int o = 16; o; o >>= 1) sum += __shfl_xor_sync(0xffffffffu, sum, o);
            if (t < CC) out[b * CC + t] = e / sum;
        }
    }
}

// ---------------------------------------------------------------------------
extern "C" void kernel_launch(void* const* d_in, const int* in_sizes, int n_in,
                              void* d_out, int out_size)
{
    const int*   X        = (const int*)  d_in[0];
    const int*   NX       = (const int*)  d_in[1];
    const int*   EW       = (const int*)  d_in[2];
    const float* node_emb = (const float*)d_in[3];
    const float* edge_w   = (const float*)d_in[4];
    const float* node_w   = (const float*)d_in[5];
    const float* fc_w     = (const float*)d_in[6];
    const float* fc_b     = (const float*)d_in[7];
    float* out = (float*)d_out;

    p_kernel<<<P1_GRID, P1_TPB>>>(node_emb, fc_w);
    dim3 grid2(GCH, BB);
    gather_kernel<<<grid2, G_TPB>>>(X, NX, EW, edge_w, node_w, fc_b, out);
}

// round 10
// speedup vs baseline: 1.0366x; 1.0366x over previous
#include <cuda_runtime.h>

#define BB 128
#define SS 512
#define KK 4
#define DD 300
#define CC 20
#define NN 10000

// K1: 32 nodes/block, thread = (pair 0..15, cg 0..3, dc 0..4) -> 320 threads
#define DSPLIT 5
#define DCH (DD / DSPLIT)          // 60
#define P1_TPB 320
#define P1_NODES 32
#define P1_GRID ((NN + P1_NODES - 1) / P1_NODES)   // 313
#define P1_THREADS (P1_GRID * P1_TPB)              // 100160

// K1 dynamic smem layout (floats)
#define TILE_F (P1_NODES * DD)     // 9600
#define FW_F   (DSPLIT * CC * DCH) // 6000
#define ACC_F  (DSPLIT * P1_NODES * CC) // 3200
#define P1_SMEM_BYTES ((TILE_F + FW_F + ACC_F) * 4)   // 75200

// K2: grid (GCH, BB), 320 threads
#define GCH 4
#define SCH (SS / GCH)             // 128
#define G_TPB 320
#define G_SGRP 16

#define EWN (BB * SS * KK)         // 262144

__device__ float g_P[NN * CC];           // P = node_emb @ fc_w^T (800 KB)
__device__ float g_EW[EWN];              // prefetched edge weights (1 MB)
__device__ float g_part[BB * GCH * CC];  // per-(b,chunk) logit partials
__device__ unsigned int g_done[BB];      // zero-init; self-resets each call

// ---------------------------------------------------------------------------
// K1: coalesced-staged P-GEMM + overlapped random edge_w prefetch.
// ---------------------------------------------------------------------------
__global__ void __launch_bounds__(P1_TPB, 2) p_kernel(
    const float* __restrict__ node_emb, const float* __restrict__ fc_w,
    const int* __restrict__ EW, const float* __restrict__ edge_w)
{
    extern __shared__ float sm[];
    float* sTile = sm;                   // [32][300]
    float* sF    = sm + TILE_F;          // [dc][c][d]
    float* sAcc  = sm + TILE_F + FW_F;   // [dc][32*20]

    const int t = threadIdx.x;

    // Stage node tile, float4-coalesced (2400 float4 by 320 threads)
    {
        const int base4 = blockIdx.x * (TILE_F / 4);
        const float4* __restrict__ src = (const float4*)node_emb;
        float4* dst = (float4*)sTile;
        #pragma unroll
        for (int j = 0; j < TILE_F / 4 / P1_TPB + 1; j++) {
            const int i = j * P1_TPB + t;
            if (i < TILE_F / 4 && base4 + i < (NN * DD) / 4)
                dst[i] = src[base4 + i];
        }
    }
    // Stage fc_w rearranged [dc][c][d-chunk]
    for (int i = t; i < FW_F; i += P1_TPB) {
        const int dc = i / (CC * DCH);
        const int r  = i % (CC * DCH);
        sF[i] = fc_w[(r / DCH) * DD + dc * DCH + (r % DCH)];
    }

    // Overlapped random edge_w prefetch: ~2.6 independent chains/thread,
    // chip-wide MLP ~262k. Writes coalesced to g_EW; visible to K2 via
    // stream order (no sync needed here).
    for (int i = blockIdx.x * P1_TPB + t; i < EWN; i += P1_THREADS)
        g_EW[i] = __ldg(&edge_w[__ldg(&EW[i])]);

    __syncthreads();

    // Compute: thread = (pair, cg, dc): 2 nodes x 5 classes x 60 d from smem
    const int dc = t / 64;
    const int w  = t % 64;
    const int pr = w >> 2;
    const int cg = w & 3;
    const int gn0 = blockIdx.x * P1_NODES + pr * 2;

    if (gn0 < NN) {                      // NN even -> pair never splits
        const float4* __restrict__ e0 = (const float4*)(sTile + (pr * 2) * DD + dc * DCH);
        const float4* __restrict__ e1 = (const float4*)(sTile + (pr * 2 + 1) * DD + dc * DCH);
        const float4* __restrict__ f4 = (const float4*)(sF + dc * CC * DCH + cg * 5 * DCH);

        float a0[5] = {0.f, 0.f, 0.f, 0.f, 0.f};
        float a1[5] = {0.f, 0.f, 0.f, 0.f, 0.f};
        #pragma unroll
        for (int dq = 0; dq < DCH / 4; dq++) {       // 15 iters
            const float4 v0 = e0[dq];
            const float4 v1 = e1[dq];
            #pragma unroll
            for (int c5 = 0; c5 < 5; c5++) {
                const float4 fv = f4[c5 * (DCH / 4) + dq];
                a0[c5] += v0.x * fv.x + v0.y * fv.y + v0.z * fv.z + v0.w * fv.w;
                a1[c5] += v1.x * fv.x + v1.y * fv.y + v1.z * fv.z + v1.w * fv.w;
            }
        }
        #pragma unroll
        for (int c5 = 0; c5 < 5; c5++) {
            sAcc[dc * (P1_NODES * CC) + (pr * 2    ) * CC + cg * 5 + c5] = a0[c5];
            sAcc[dc * (P1_NODES * CC) + (pr * 2 + 1) * CC + cg * 5 + c5] = a1[c5];
        }
    }
    __syncthreads();

    // Reduce 5 d-chunk partials, coalesced write
    const int base = blockIdx.x * P1_NODES * CC;
    for (int i = t; i < P1_NODES * CC; i += P1_TPB) {
        if (base + i < NN * CC) {
            float s = sAcc[i];
            #pragma unroll
            for (int d = 1; d < DSPLIT; d++) s += sAcc[d * (P1_NODES * CC) + i];
            g_P[base + i] = s;
        }
    }
}

// ---------------------------------------------------------------------------
// K2: gather on P (L2) with prefetched edge weights; last-arriver finalizes.
// ---------------------------------------------------------------------------
__global__ void __launch_bounds__(G_TPB) gather_kernel(
    const int* __restrict__ X, const int* __restrict__ NX,
    const float* __restrict__ node_w,
    const float* __restrict__ fc_b, float* __restrict__ out)
{
    __shared__ int   sX[SCH];
    __shared__ float sNW[SCH];
    __shared__ int   sNX[SCH * KK];
    __shared__ float sEW[SCH * KK];
    __shared__ float sred[G_SGRP][CC];

    const int ch = blockIdx.x;
    const int b  = blockIdx.y;
    const int s0 = ch * SCH;
    const int t  = threadIdx.x;

    // All staging loads coalesced (edge weights already resolved into g_EW)
    for (int i = t; i < SCH * KK; i += G_TPB) sEW[i] = g_EW[(b * SS + s0) * KK + i];
    for (int i = t; i < SCH * KK; i += G_TPB) sNX[i] = NX[(b * SS + s0) * KK + i];
    for (int i = t; i < SCH; i += G_TPB)      sX[i]  = X[b * SS + s0 + i];
    __syncthreads();
    for (int i = t; i < SCH; i += G_TPB)      sNW[i] = __ldg(&node_w[sX[i]]);
    __syncthreads();

    const int g = t / CC, c = t % CC;
    float acc = 0.f;
    #pragma unroll 4
    for (int i = 0; i < SCH / G_SGRP; i++) {       // 8
        const int s = g + i * G_SGRP;
        const float nw = sNW[s];
        float m = 0.f;
        #pragma unroll
        for (int k = 0; k < KK; k++)
            m += sEW[s * KK + k] * __ldg(&g_P[sNX[s * KK + k] * CC + c]);
        acc += (1.f - nw) * m + nw * __ldg(&g_P[sX[s] * CC + c]);
    }
    sred[g][c] = acc;
    __syncthreads();

    #pragma unroll
    for (int off = G_SGRP / 2; off > 0; off >>= 1) {
        if (g < off) sred[g][c] += sred[g + off][c];
        __syncthreads();
    }

    if (t < CC) g_part[(b * GCH + ch) * CC + t] = sred[0][t];
    __syncthreads();

    if (t < 32) {
        unsigned last = 0;
        if (t == 0) {
            __threadfence();
            last = (atomicAdd(&g_done[b], 1u) == GCH - 1) ? 1u : 0u;
        }
        last = __shfl_sync(0xffffffffu, last, 0);
        if (last) {
            if (t == 0) {
                g_done[b] = 0;                     // reset for graph replay
                __threadfence();
            }
            __syncwarp();
            float l = -1e30f;
            if (t < CC) {
                float s = fc_b[t];
                #pragma unroll
                for (int q = 0; q < GCH; q++)
                    s += g_part[(b * GCH + q) * CC + t];
                l = fmaxf(s, 0.f);
            }
            float mx = l;
            #pragma unroll
            for (int o = 16; o; o >>= 1) mx = fmaxf(mx, __shfl_xor_sync(0xffffffffu, mx, o));
            const float e = (t < CC) ? __expf(l - mx) : 0.f;
            float sum = e;
            #pragma unroll
            for (int o = 16; o; o >>= 1) sum += __shfl_xor_sync(0xffffffffu, sum, o);
            if (t < CC) out[b * CC + t] = e / sum;
        }
    }
}

// ---------------------------------------------------------------------------
extern "C" void kernel_launch(void* const* d_in, const int* in_sizes, int n_in,
                              void* d_out, int out_size)
{
    const int*   X        = (const int*)  d_in[0];
    const int*   NX       = (const int*)  d_in[1];
    const int*   EW       = (const int*)  d_in[2];
    const float* node_emb = (const float*)d_in[3];
    const float* edge_w   = (const float*)d_in[4];
    const float* node_w   = (const float*)d_in[5];
    const float* fc_w     = (const float*)d_in[6];
    const float* fc_b     = (const float*)d_in[7];
    float* out = (float*)d_out;

    cudaFuncSetAttribute(p_kernel, cudaFuncAttributeMaxDynamicSharedMemorySize,
                         P1_SMEM_BYTES);

    p_kernel<<<P1_GRID, P1_TPB, P1_SMEM_BYTES>>>(node_emb, fc_w, EW, edge_w);
    dim3 grid2(GCH, BB);
    gather_kernel<<<grid2, G_TPB>>>(X, NX, node_w, fc_b, out);
}

// round 11
// speedup vs baseline: 1.1380x; 1.0978x over previous
#include <cuda_runtime.h>

#define BB 128
#define SS 512
#define KK 4
#define DD 300
#define CC 20
#define NN 10000

// K1: 32 nodes/block; thread = (dc 0..2, pair 0..15, cg 0..3) -> 192 threads
#define DSPLIT 3
#define DCH (DD / DSPLIT)          // 100
#define P1_TPB 192
#define P1_NODES 32
#define P1_GRID ((NN + P1_NODES - 1) / P1_NODES)   // 313
#define P1_THREADS (P1_GRID * P1_TPB)              // 60096

// K2: grid (GCH, BB), 320 threads; thread = (group 0..63, quad 0..4)
#define GCH 4
#define SCH (SS / GCH)             // 128
#define G_TPB 320
#define G_GRP 64                   // s-groups (320 / 5)

#define EWN (BB * SS * KK)         // 262144

__device__ float g_P[NN * CC];           // P = node_emb @ fc_w^T (800 KB)
__device__ float g_EW[EWN];              // prefetched edge weights (1 MB)
__device__ float g_part[BB * GCH * CC];  // per-(b,chunk) logit partials
__device__ unsigned int g_done[BB];      // zero-init; self-resets each call

// ---------------------------------------------------------------------------
// K1: P-GEMM (pairs x 5 classes x 3 d-chunks) + overlapped random edge_w
// prefetch. Per 4d iter: 2 LDG.128 + 5 LDS.128 + 40 FFMA  (LDS ~ FMA balance).
// ---------------------------------------------------------------------------
__global__ void __launch_bounds__(P1_TPB, 4) p_kernel(
    const float* __restrict__ node_emb, const float* __restrict__ fc_w,
    const int* __restrict__ EW, const float* __restrict__ edge_w)
{
    __shared__ float sF[DSPLIT * CC * DCH];          // 24 KB, [dc][c][d]
    __shared__ float sAcc[DSPLIT][P1_NODES * CC];    // 7.7 KB

    const int t = threadIdx.x;

    // Stage fc_w rearranged [dc][c][d-within-chunk]
    for (int i = t; i < DSPLIT * CC * DCH; i += P1_TPB) {
        const int dc = i / (CC * DCH);
        const int r  = i % (CC * DCH);
        sF[i] = fc_w[(r / DCH) * DD + dc * DCH + (r % DCH)];
    }

    // Overlapped random edge_w prefetch (~4.4 independent chains/thread);
    // coalesced writes to g_EW, consumed by K2 via stream order.
    for (int i = blockIdx.x * P1_TPB + t; i < EWN; i += P1_THREADS)
        g_EW[i] = __ldg(&edge_w[__ldg(&EW[i])]);

    __syncthreads();

    const int dc = t / 64;                 // 0..2
    const int w  = t % 64;
    const int pr = w >> 2;                 // 0..15 node-pair
    const int cg = w & 3;                  // 0..3  class-group (5 classes)
    const int n0 = blockIdx.x * P1_NODES + pr * 2;
    const int d0 = dc * DCH;

    if (n0 < NN) {                         // NN even -> pair never splits
        const float4* __restrict__ e0 = (const float4*)(node_emb + (size_t)n0 * DD + d0);
        const float4* __restrict__ e1 = (const float4*)(node_emb + (size_t)(n0 + 1) * DD + d0);
        const float4* __restrict__ f4 = (const float4*)(sF + dc * CC * DCH + cg * 5 * DCH);

        float a0[5] = {0.f, 0.f, 0.f, 0.f, 0.f};
        float a1[5] = {0.f, 0.f, 0.f, 0.f, 0.f};
        #pragma unroll 5
        for (int dq = 0; dq < DCH / 4; dq++) {       // 25 iters
            const float4 v0 = e0[dq];
            const float4 v1 = e1[dq];
            #pragma unroll
            for (int c5 = 0; c5 < 5; c5++) {
                const float4 fv = f4[c5 * (DCH / 4) + dq];
                a0[c5] += v0.x * fv.x + v0.y * fv.y + v0.z * fv.z + v0.w * fv.w;
                a1[c5] += v1.x * fv.x + v1.y * fv.y + v1.z * fv.z + v1.w * fv.w;
            }
        }
        #pragma unroll
        for (int c5 = 0; c5 < 5; c5++) {
            sAcc[dc][(pr * 2    ) * CC + cg * 5 + c5] = a0[c5];
            sAcc[dc][(pr * 2 + 1) * CC + cg * 5 + c5] = a1[c5];
        }
    }
    __syncthreads();

    // Reduce 3 d-chunk partials, coalesced write
    const int base = blockIdx.x * P1_NODES * CC;
    for (int i = t; i < P1_NODES * CC; i += P1_TPB) {
        if (base + i < NN * CC) {
            g_P[base + i] = sAcc[0][i] + sAcc[1][i] + sAcc[2][i];
        }
    }
}

// ---------------------------------------------------------------------------
// K2: vectorized gather on P. Thread = (s-group g, quad q): q covers classes
// 4q..4q+3 as one float4 -> 10 LDG.128/thread instead of 40 LDG.32.
// Last-arriving chunk block per b combines partials + softmax.
// ---------------------------------------------------------------------------
__global__ void __launch_bounds__(G_TPB) gather_kernel(
    const int* __restrict__ X, const int* __restrict__ NX,
    const float* __restrict__ node_w,
    const float* __restrict__ fc_b, float* __restrict__ out)
{
    __shared__ int   sX[SCH];
    __shared__ float sNW[SCH];
    __shared__ int   sNX[SCH * KK];
    __shared__ float sEW[SCH * KK];
    __shared__ float sred[G_GRP][CC];      // 5 KB

    const int ch = blockIdx.x;
    const int b  = blockIdx.y;
    const int s0 = ch * SCH;
    const int t  = threadIdx.x;

    // Coalesced staging (edge weights pre-resolved in g_EW by K1)
    for (int i = t; i < SCH * KK; i += G_TPB) sEW[i] = g_EW[(b * SS + s0) * KK + i];
    for (int i = t; i < SCH * KK; i += G_TPB) sNX[i] = NX[(b * SS + s0) * KK + i];
    for (int i = t; i < SCH; i += G_TPB)      sX[i]  = X[b * SS + s0 + i];
    __syncthreads();
    for (int i = t; i < SCH; i += G_TPB)      sNW[i] = __ldg(&node_w[sX[i]]);
    __syncthreads();

    const int g = t / 5;                   // 0..63 s-group
    const int q = t % 5;                   // 0..4  class quad
    const float4* __restrict__ P4 = (const float4*)g_P;   // row stride 5

    float4 acc = make_float4(0.f, 0.f, 0.f, 0.f);
    #pragma unroll
    for (int i = 0; i < SCH / G_GRP; i++) {        // 2 s-positions per thread
        const int s = g + i * G_GRP;
        const float nw = sNW[s];
        float4 m = make_float4(0.f, 0.f, 0.f, 0.f);
        #pragma unroll
        for (int k = 0; k < KK; k++) {
            const float  ew = sEW[s * KK + k];
            const float4 p  = __ldg(&P4[sNX[s * KK + k] * 5 + q]);
            m.x += ew * p.x; m.y += ew * p.y; m.z += ew * p.z; m.w += ew * p.w;
        }
        const float4 r = __ldg(&P4[sX[s] * 5 + q]);
        const float inw = 1.f - nw;
        acc.x += inw * m.x + nw * r.x;
        acc.y += inw * m.y + nw * r.y;
        acc.z += inw * m.z + nw * r.z;
        acc.w += inw * m.w + nw * r.w;
    }
    *(float4*)&sred[g][q * 4] = acc;
    __syncthreads();

    // Fixed-order tree reduce over 64 s-groups (float4 lanes) -> deterministic
    #pragma unroll
    for (int off = G_GRP / 2; off > 0; off >>= 1) {
        if (t < off * 5) {
            const int gg = t / 5, qq = t % 5;
            float4 a = *(float4*)&sred[gg][qq * 4];
            float4 bb = *(float4*)&sred[gg + off][qq * 4];
            a.x += bb.x; a.y += bb.y; a.z += bb.z; a.w += bb.w;
            *(float4*)&sred[gg][qq * 4] = a;
        }
        __syncthreads();
    }

    if (t < CC) g_part[(b * GCH + ch) * CC + t] = sred[0][t];
    __syncthreads();

    if (t < 32) {
        unsigned last = 0;
        if (t == 0) {
            __threadfence();                               // release my partial
            last = (atomicAdd(&g_done[b], 1u) == GCH - 1) ? 1u : 0u;
        }
        last = __shfl_sync(0xffffffffu, last, 0);
        if (last) {
            if (t == 0) {
                g_done[b] = 0;                             // reset for replay
                __threadfence();                           // acquire partials
            }
            __syncwarp();
            float l = -1e30f;
            if (t < CC) {
                float s = fc_b[t];
                #pragma unroll
                for (int qch = 0; qch < GCH; qch++)
                    s += g_part[(b * GCH + qch) * CC + t];
                l = fmaxf(s, 0.f);
            }
            float mx = l;
            #pragma unroll
            for (int o = 16; o; o >>= 1) mx = fmaxf(mx, __shfl_xor_sync(0xffffffffu, mx, o));
            const float e = (t < CC) ? __expf(l - mx) : 0.f;
            float sum = e;
            #pragma unroll
            for (int o = 16; o; o >>= 1) sum += __shfl_xor_sync(0xffffffffu, sum, o);
            if (t < CC) out[b * CC + t] = e / sum;
        }
    }
}

// ---------------------------------------------------------------------------
extern "C" void kernel_launch(void* const* d_in, const int* in_sizes, int n_in,
                              void* d_out, int out_size)
{
    const int*   X        = (const int*)  d_in[0];
    const int*   NX       = (const int*)  d_in[1];
    const int*   EW       = (const int*)  d_in[2];
    const float* node_emb = (const float*)d_in[3];
    const float* edge_w   = (const float*)d_in[4];
    const float* node_w   = (const float*)d_in[5];
    const float* fc_w     = (const float*)d_in[6];
    const float* fc_b     = (const float*)d_in[7];
    float* out = (float*)d_out;

    p_kernel<<<P1_GRID, P1_TPB>>>(node_emb, fc_w, EW, edge_w);
    dim3 grid2(GCH, BB);
    gather_kernel<<<grid2, G_TPB>>>(X, NX, node_w, fc_b, out);
}